// round 1
// baseline (speedup 1.0000x reference)
#include <cuda_runtime.h>
#include <cstdint>

#define NROWS 16384
#define DDIM  32
#define HDIM  128
#define BK    32

// Scratch (device globals: no allocations allowed)
__device__ float g_msgT[DDIM * NROWS];   // messages TRANSPOSED: [d][row]
__device__ float g_agg [NROWS * DDIM];   // degree-normalized aggregation [row][d]

// ---------------- packed f32x2 helpers ----------------
__device__ __forceinline__ unsigned long long ffma2(unsigned long long a,
                                                    unsigned long long b,
                                                    unsigned long long c) {
    unsigned long long d;
    asm("fma.rn.f32x2 %0, %1, %2, %3;" : "=l"(d) : "l"(a), "l"(b), "l"(c));
    return d;
}
__device__ __forceinline__ unsigned long long fadd2(unsigned long long a,
                                                    unsigned long long b) {
    unsigned long long d;
    asm("add.rn.f32x2 %0, %1, %2;" : "=l"(d) : "l"(a), "l"(b));
    return d;
}
__device__ __forceinline__ void upk2(unsigned long long v, float& lo, float& hi) {
    asm("mov.b64 {%0,%1}, %2;" : "=f"(lo), "=f"(hi) : "l"(v));
}
__device__ __forceinline__ void cp16(uint32_t dst, const void* src) {
    asm volatile("cp.async.cg.shared.global [%0], [%1], 16;" :: "r"(dst), "l"(src) : "memory");
}

// ==================== Kernel 1: message MLP ====================
// messages = relu(states @ mW1 + mb1) @ mW2 + mb2, written TRANSPOSED to g_msgT
__global__ __launch_bounds__(128) void msg_kernel(
    const float* __restrict__ states, const float* __restrict__ W1,
    const float* __restrict__ b1,     const float* __restrict__ W2,
    const float* __restrict__ b2)
{
    __shared__ float sW1[DDIM * HDIM];   // [j][h] 16KB
    __shared__ float sW2[HDIM * DDIM];   // [h][d] 16KB
    const int tid = threadIdx.x;
    for (int i = tid; i < DDIM * HDIM; i += 128) sW1[i] = W1[i];
    for (int i = tid; i < HDIM * DDIM; i += 128) sW2[i] = W2[i];
    __syncthreads();

    const int row = blockIdx.x * 128 + tid;
    float s[DDIM];
    const float4* sp = reinterpret_cast<const float4*>(states + (size_t)row * DDIM);
    #pragma unroll
    for (int j4 = 0; j4 < DDIM / 4; j4++) {
        float4 v = sp[j4];
        s[4*j4+0] = v.x; s[4*j4+1] = v.y; s[4*j4+2] = v.z; s[4*j4+3] = v.w;
    }
    float m[DDIM];
    #pragma unroll
    for (int d = 0; d < DDIM; d++) m[d] = __ldg(&b2[d]);

    #pragma unroll 2
    for (int hg = 0; hg < HDIM / 4; hg++) {
        float4 hid = __ldg(reinterpret_cast<const float4*>(b1) + hg);
        #pragma unroll
        for (int j = 0; j < DDIM; j++) {
            float4 w = *reinterpret_cast<const float4*>(&sW1[j * HDIM + 4 * hg]);
            hid.x += s[j] * w.x; hid.y += s[j] * w.y;
            hid.z += s[j] * w.z; hid.w += s[j] * w.w;
        }
        float r0 = fmaxf(hid.x, 0.f), r1 = fmaxf(hid.y, 0.f);
        float r2 = fmaxf(hid.z, 0.f), r3 = fmaxf(hid.w, 0.f);
        float rr[4] = {r0, r1, r2, r3};
        #pragma unroll
        for (int e = 0; e < 4; e++) {
            float r = rr[e];
            #pragma unroll
            for (int d4 = 0; d4 < DDIM / 4; d4++) {
                float4 w = *reinterpret_cast<const float4*>(&sW2[(4*hg+e) * DDIM + 4*d4]);
                m[4*d4+0] += r * w.x; m[4*d4+1] += r * w.y;
                m[4*d4+2] += r * w.z; m[4*d4+3] += r * w.w;
            }
        }
    }
    // transposed store: per d, lanes write consecutive rows -> coalesced
    #pragma unroll
    for (int d = 0; d < DDIM; d++)
        g_msgT[(size_t)d * NROWS + row] = m[d];
}

// ==================== Kernel 2: fused degree + aggregation GEMM ====================
// g_agg[r][:] = (adj[r][:] @ messages) / max(rowsum(adj[r]), 1)
// Block: 256 thr, tile 128 rows x 32 cols, full K. warp = colgroup (4 cols),
// lane = base row (rows lane+32i). f32x2 accumulators paired along K.
__device__ __forceinline__ void prefetch_tiles(const float* __restrict__ adj,
        size_t rowBase, int kt, float4* sAbuf, float4* sBbuf, int tid)
{
    const float* base = adj + rowBase * NROWS + (size_t)kt * BK;
    #pragma unroll
    for (int i = 0; i < 4; i++) {
        int f = tid + 256 * i;
        int row = f >> 3, kc = f & 7;
        uint32_t dst = (uint32_t)__cvta_generic_to_shared(
            sAbuf + row * 8 + (kc ^ (row & 7)));            // XOR swizzle
        cp16(dst, base + (size_t)row * NROWS + (kc << 2));
    }
    int c = tid >> 3, kq = tid & 7;
    uint32_t dstB = (uint32_t)__cvta_generic_to_shared(sBbuf + tid);
    cp16(dstB, &g_msgT[(size_t)c * NROWS + (size_t)kt * BK + (kq << 2)]);
    asm volatile("cp.async.commit_group;" ::: "memory");
}

__global__ __launch_bounds__(256, 1) void agg_kernel(const float* __restrict__ adj)
{
    __shared__ float4 sA[2][128 * 8];   // [row][kc^swizzle]  32KB
    __shared__ float4 sB[2][32 * 8];    // msgT tile [c][kq]   8KB
    __shared__ float  sdeg[128];

    const int tid  = threadIdx.x;
    const int warp = tid >> 5;       // colgroup: cols warp*4..warp*4+3
    const int lane = tid & 31;       // rows lane + 32*i
    const int sw   = lane & 7;
    const size_t rowBase = (size_t)blockIdx.x * 128;

    unsigned long long acc[4][4];    // (even-k partial, odd-k partial)
    unsigned long long sum2[4];
    #pragma unroll
    for (int i = 0; i < 4; i++) {
        sum2[i] = 0ULL;
        #pragma unroll
        for (int c = 0; c < 4; c++) acc[i][c] = 0ULL;
    }

    prefetch_tiles(adj, rowBase, 0, sA[0], sB[0], tid);

    const int NT = NROWS / BK;  // 512
    for (int kt = 0; kt < NT; kt++) {
        const int buf = kt & 1;
        if (kt + 1 < NT) {
            prefetch_tiles(adj, rowBase, kt + 1, sA[buf ^ 1], sB[buf ^ 1], tid);
            asm volatile("cp.async.wait_group 1;" ::: "memory");
        } else {
            asm volatile("cp.async.wait_group 0;" ::: "memory");
        }
        __syncthreads();

        const ulonglong2* pA = reinterpret_cast<const ulonglong2*>(&sA[buf][0]);
        const ulonglong2* pB = reinterpret_cast<const ulonglong2*>(&sB[buf][0]);

        #pragma unroll
        for (int kc = 0; kc < 8; kc++) {
            ulonglong2 bq[4];
            #pragma unroll
            for (int c = 0; c < 4; c++)
                bq[c] = pB[(warp * 4 + c) * 8 + kc];    // warp-uniform -> broadcast
            #pragma unroll
            for (int i = 0; i < 4; i++) {
                ulonglong2 aq = pA[(lane + 32 * i) * 8 + (kc ^ sw)];
                #pragma unroll
                for (int c = 0; c < 4; c++) {
                    acc[i][c] = ffma2(aq.x, bq[c].x, acc[i][c]);
                    acc[i][c] = ffma2(aq.y, bq[c].y, acc[i][c]);
                }
                if (warp == 0) {                         // rowsum (degree), once per row
                    sum2[i] = fadd2(sum2[i], aq.x);
                    sum2[i] = fadd2(sum2[i], aq.y);
                }
            }
        }
        __syncthreads();
    }

    if (warp == 0) {
        #pragma unroll
        for (int i = 0; i < 4; i++) {
            float lo, hi; upk2(sum2[i], lo, hi);
            sdeg[lane + 32 * i] = lo + hi;
        }
    }
    __syncthreads();

    #pragma unroll
    for (int i = 0; i < 4; i++) {
        int row = lane + 32 * i;
        float rd = 1.0f / fmaxf(sdeg[row], 1.0f);
        float lo, hi;
        float4 o;
        upk2(acc[i][0], lo, hi); o.x = (lo + hi) * rd;
        upk2(acc[i][1], lo, hi); o.y = (lo + hi) * rd;
        upk2(acc[i][2], lo, hi); o.z = (lo + hi) * rd;
        upk2(acc[i][3], lo, hi); o.w = (lo + hi) * rd;
        *reinterpret_cast<float4*>(&g_agg[((size_t)rowBase + row) * DDIM + warp * 4]) = o;
    }
}

// ==================== Kernel 3: update MLP ====================
// out = relu([states, agg] @ uW1 + ub1) @ uW2 + ub2
__global__ __launch_bounds__(128) void upd_kernel(
    const float* __restrict__ states, const float* __restrict__ W1,
    const float* __restrict__ b1,     const float* __restrict__ W2,
    const float* __restrict__ b2,     float* __restrict__ out)
{
    __shared__ float sW1[2 * DDIM * HDIM];  // [j][h] 32KB
    __shared__ float sW2[HDIM * DDIM];      // [h][d] 16KB
    const int tid = threadIdx.x;
    for (int i = tid; i < 2 * DDIM * HDIM; i += 128) sW1[i] = W1[i];
    for (int i = tid; i < HDIM * DDIM; i += 128)     sW2[i] = W2[i];
    __syncthreads();

    const int row = blockIdx.x * 128 + tid;
    float x[2 * DDIM];
    const float4* sp = reinterpret_cast<const float4*>(states + (size_t)row * DDIM);
    const float4* gp = reinterpret_cast<const float4*>(g_agg  + (size_t)row * DDIM);
    #pragma unroll
    for (int j4 = 0; j4 < DDIM / 4; j4++) {
        float4 v = sp[j4];
        x[4*j4+0] = v.x; x[4*j4+1] = v.y; x[4*j4+2] = v.z; x[4*j4+3] = v.w;
        float4 g = gp[j4];
        x[DDIM+4*j4+0] = g.x; x[DDIM+4*j4+1] = g.y;
        x[DDIM+4*j4+2] = g.z; x[DDIM+4*j4+3] = g.w;
    }
    float m[DDIM];
    #pragma unroll
    for (int d = 0; d < DDIM; d++) m[d] = __ldg(&b2[d]);

    #pragma unroll 2
    for (int hg = 0; hg < HDIM / 4; hg++) {
        float4 hid = __ldg(reinterpret_cast<const float4*>(b1) + hg);
        #pragma unroll
        for (int j = 0; j < 2 * DDIM; j++) {
            float4 w = *reinterpret_cast<const float4*>(&sW1[j * HDIM + 4 * hg]);
            hid.x += x[j] * w.x; hid.y += x[j] * w.y;
            hid.z += x[j] * w.z; hid.w += x[j] * w.w;
        }
        float rr[4] = {fmaxf(hid.x, 0.f), fmaxf(hid.y, 0.f),
                       fmaxf(hid.z, 0.f), fmaxf(hid.w, 0.f)};
        #pragma unroll
        for (int e = 0; e < 4; e++) {
            float r = rr[e];
            #pragma unroll
            for (int d4 = 0; d4 < DDIM / 4; d4++) {
                float4 w = *reinterpret_cast<const float4*>(&sW2[(4*hg+e) * DDIM + 4*d4]);
                m[4*d4+0] += r * w.x; m[4*d4+1] += r * w.y;
                m[4*d4+2] += r * w.z; m[4*d4+3] += r * w.w;
            }
        }
    }
    float4* op = reinterpret_cast<float4*>(out + (size_t)row * DDIM);
    #pragma unroll
    for (int d4 = 0; d4 < DDIM / 4; d4++) {
        float4 o;
        o.x = m[4*d4+0]; o.y = m[4*d4+1]; o.z = m[4*d4+2]; o.w = m[4*d4+3];
        op[d4] = o;
    }
}

// ==================== launch ====================
extern "C" void kernel_launch(void* const* d_in, const int* in_sizes, int n_in,
                              void* d_out, int out_size)
{
    const float* states = (const float*)d_in[0];
    const float* adj    = (const float*)d_in[1];
    const float* mW1    = (const float*)d_in[2];
    const float* mb1    = (const float*)d_in[3];
    const float* mW2    = (const float*)d_in[4];
    const float* mb2    = (const float*)d_in[5];
    const float* uW1    = (const float*)d_in[6];
    const float* ub1    = (const float*)d_in[7];
    const float* uW2    = (const float*)d_in[8];
    const float* ub2    = (const float*)d_in[9];
    float* out = (float*)d_out;

    msg_kernel<<<NROWS / 128, 128>>>(states, mW1, mb1, mW2, mb2);
    agg_kernel<<<NROWS / 128, 256>>>(adj);
    upd_kernel<<<NROWS / 128, 128>>>(states, uW1, ub1, uW2, ub2, out);
}

// round 3
// speedup vs baseline: 2.1870x; 2.1870x over previous
#include <cuda_runtime.h>
#include <cstdint>

#define NROWS 16384
#define DDIM  32
#define HDIM  128
#define BK    32                 // K floats per stage -> 128B rows
#define BN    48                 // 32 msg cols + degree col(32) + pad to 6 n8-tiles
#define STAGES 8
#define NT    (NROWS / BK)       // 512
#define ABYTES (128 * 128)       // 128 rows x 128B = 16384
#define BBYTES (BN * 128)        // 48 rows x 128B  = 6144
#define STAGE_BYTES (ABYTES + BBYTES)               // 22528
#define SMEM_TOTAL  (1024 + STAGES * STAGE_BYTES)   // 181248

// device scratch
__device__ float g_msgB[BN * NROWS];   // [col][k], tf32-rna for cols 0..31, col32=1, rest 0
__device__ float g_agg [NROWS * DDIM];

// ---------------- PTX helpers ----------------
__device__ __forceinline__ void cp16(uint32_t dst, const void* src) {
    asm volatile("cp.async.cg.shared.global [%0], [%1], 16;" :: "r"(dst), "l"(src) : "memory");
}
__device__ __forceinline__ float tf32_rna(float x) {
    uint32_t r;
    asm("cvt.rna.tf32.f32 %0, %1;" : "=r"(r) : "f"(x));
    return __uint_as_float(r);
}
__device__ __forceinline__ void ldsm_x4(uint32_t& r0, uint32_t& r1, uint32_t& r2, uint32_t& r3,
                                        uint32_t addr) {
    asm volatile("ldmatrix.sync.aligned.m8n8.x4.shared.b16 {%0,%1,%2,%3}, [%4];"
                 : "=r"(r0), "=r"(r1), "=r"(r2), "=r"(r3) : "r"(addr));
}
__device__ __forceinline__ void mma_tf32(float* c, uint32_t a0, uint32_t a1,
                                         uint32_t a2, uint32_t a3,
                                         uint32_t b0, uint32_t b1) {
    asm volatile(
        "mma.sync.aligned.m16n8k8.row.col.f32.tf32.tf32.f32 "
        "{%0,%1,%2,%3}, {%4,%5,%6,%7}, {%8,%9}, {%0,%1,%2,%3};"
        : "+f"(c[0]), "+f"(c[1]), "+f"(c[2]), "+f"(c[3])
        : "r"(a0), "r"(a1), "r"(a2), "r"(a3), "r"(b0), "r"(b1));
}

// ==================== Kernel 1: message MLP -> tf32 B plane ====================
__global__ __launch_bounds__(128) void msg_kernel(
    const float* __restrict__ states, const float* __restrict__ W1,
    const float* __restrict__ b1,     const float* __restrict__ W2,
    const float* __restrict__ b2)
{
    __shared__ float sW1[DDIM * HDIM];
    __shared__ float sW2[HDIM * DDIM];
    const int tid = threadIdx.x;
    for (int i = tid; i < DDIM * HDIM; i += 128) sW1[i] = W1[i];
    for (int i = tid; i < HDIM * DDIM; i += 128) sW2[i] = W2[i];
    __syncthreads();

    const int row = blockIdx.x * 128 + tid;
    float s[DDIM];
    const float4* sp = reinterpret_cast<const float4*>(states + (size_t)row * DDIM);
    #pragma unroll
    for (int j4 = 0; j4 < DDIM / 4; j4++) {
        float4 v = sp[j4];
        s[4*j4+0] = v.x; s[4*j4+1] = v.y; s[4*j4+2] = v.z; s[4*j4+3] = v.w;
    }
    float m[DDIM];
    #pragma unroll
    for (int d = 0; d < DDIM; d++) m[d] = __ldg(&b2[d]);

    #pragma unroll 2
    for (int hg = 0; hg < HDIM / 4; hg++) {
        float4 hid = __ldg(reinterpret_cast<const float4*>(b1) + hg);
        #pragma unroll
        for (int j = 0; j < DDIM; j++) {
            float4 w = *reinterpret_cast<const float4*>(&sW1[j * HDIM + 4 * hg]);
            hid.x += s[j] * w.x; hid.y += s[j] * w.y;
            hid.z += s[j] * w.z; hid.w += s[j] * w.w;
        }
        float rr[4] = {fmaxf(hid.x, 0.f), fmaxf(hid.y, 0.f),
                       fmaxf(hid.z, 0.f), fmaxf(hid.w, 0.f)};
        #pragma unroll
        for (int e = 0; e < 4; e++) {
            float r = rr[e];
            #pragma unroll
            for (int d4 = 0; d4 < DDIM / 4; d4++) {
                float4 w = *reinterpret_cast<const float4*>(&sW2[(4*hg+e) * DDIM + 4*d4]);
                m[4*d4+0] += r * w.x; m[4*d4+1] += r * w.y;
                m[4*d4+2] += r * w.z; m[4*d4+3] += r * w.w;
            }
        }
    }
    #pragma unroll
    for (int d = 0; d < DDIM; d++)
        g_msgB[(size_t)d * NROWS + row] = tf32_rna(m[d]);
    g_msgB[(size_t)32 * NROWS + row] = 1.0f;          // degree column
    #pragma unroll
    for (int d = 33; d < BN; d++)
        g_msgB[(size_t)d * NROWS + row] = 0.0f;       // pad
}

// ==================== Kernel 2: tf32 mma.sync aggregation + fused degree ====================
__device__ __forceinline__ void fill_stage(const float* __restrict__ adj, size_t rowBase,
                                           int tile, uint32_t stage, int tid)
{
    const float* aSrc = adj + rowBase * NROWS + (size_t)tile * BK;
    #pragma unroll
    for (int i = 0; i < 4; i++) {                     // A: 1024 16B chunks
        int c = tid + 256 * i;
        int r = c >> 3, k4 = c & 7;
        uint32_t dst = stage + ((r * 8 + (k4 ^ (r & 7))) << 4);
        cp16(dst, aSrc + (size_t)r * NROWS + (k4 << 2));
    }
    {                                                 // B: 384 chunks
        int c = tid;
        int r = c >> 3, k4 = c & 7;
        uint32_t dst = stage + ABYTES + ((r * 8 + (k4 ^ (r & 7))) << 4);
        cp16(dst, g_msgB + (size_t)r * NROWS + (size_t)tile * BK + (k4 << 2));
        c = tid + 256;
        if (c < BN * 8) {
            r = c >> 3; k4 = c & 7;
            dst = stage + ABYTES + ((r * 8 + (k4 ^ (r & 7))) << 4);
            cp16(dst, g_msgB + (size_t)r * NROWS + (size_t)tile * BK + (k4 << 2));
        }
    }
    asm volatile("cp.async.commit_group;" ::: "memory");
}

__global__ __launch_bounds__(256, 1) void agg_kernel(const float* __restrict__ adj)
{
    extern __shared__ char smem[];
    uint32_t sraw = (uint32_t)__cvta_generic_to_shared(smem);
    const uint32_t stage0 = (sraw + 1023u) & ~1023u;

    const int tid  = threadIdx.x;
    const int wid  = tid >> 5;
    const int lane = tid & 31;
    const size_t rowBase = (size_t)blockIdx.x * 128;

    // ldmatrix addressing components (constant over k-steps except chunk)
    const int jm = lane >> 3;        // matrix index 0..3
    const int qm = lane & 7;         // row within matrix
    const int arow = wid * 16 + (jm >> 1) * 8 + qm;    // A row for this lane

    float acc[5][4];
    #pragma unroll
    for (int nt = 0; nt < 5; nt++)
        #pragma unroll
        for (int e = 0; e < 4; e++) acc[nt][e] = 0.f;

    // prologue: stages 0..6
    for (int t = 0; t < STAGES - 1; t++)
        fill_stage(adj, rowBase, t, stage0 + t * STAGE_BYTES, tid);

    for (int kt = 0; kt < NT; kt++) {
        asm volatile("cp.async.wait_group %0;" :: "n"(STAGES - 2) : "memory");
        __syncthreads();

        const uint32_t sA = stage0 + (uint32_t)(kt & (STAGES - 1)) * STAGE_BYTES;
        const uint32_t sB = sA + ABYTES;

        #pragma unroll
        for (int s = 0; s < 4; s++) {
            const int ch = 2 * s + (jm & 1);
            // A fragment (m16 x k8)
            uint32_t a0, a1, a2, a3;
            ldsm_x4(a0, a1, a2, a3, sA + ((arow * 8 + (ch ^ (arow & 7))) << 4));
            // B fragments: 3 x (two n8-tiles each)
            uint32_t b[12];
            #pragma unroll
            for (int g = 0; g < 3; g++) {
                const int nrow = g * 16 + (jm >> 1) * 8 + qm;
                ldsm_x4(b[4*g+0], b[4*g+1], b[4*g+2], b[4*g+3],
                        sB + ((nrow * 8 + (ch ^ (nrow & 7))) << 4));
            }
            // mma: reg permutation r0,r2,r1,r3 = a0,a1,a2,a3
            #pragma unroll
            for (int nt = 0; nt < 5; nt++) {
                const uint32_t b0 = b[(nt >> 1) * 4 + (nt & 1) * 2];
                const uint32_t b1 = b[(nt >> 1) * 4 + (nt & 1) * 2 + 1];
                mma_tf32(acc[nt], a0, a2, a1, a3, b0, b1);
            }
        }

        const int nxt = kt + STAGES - 1;
        if (nxt < NT)
            fill_stage(adj, rowBase, nxt, stage0 + (uint32_t)(nxt & (STAGES - 1)) * STAGE_BYTES, tid);
    }

    // degree = column 32 = n-tile 4, col offset 0 (held by lanes with lane%4==0)
    const int srcLane = lane & ~3;
    float dlo = __shfl_sync(0xffffffffu, acc[4][0], srcLane);
    float dhi = __shfl_sync(0xffffffffu, acc[4][2], srcLane);
    float rdlo = 1.0f / fmaxf(dlo, 1.0f);
    float rdhi = 1.0f / fmaxf(dhi, 1.0f);

    const size_t rlo = rowBase + (size_t)(wid * 16 + (lane >> 2));
    const size_t rhi = rlo + 8;
    const int coff = 2 * (lane & 3);
    #pragma unroll
    for (int nt = 0; nt < 4; nt++) {
        float2 olo = {acc[nt][0] * rdlo, acc[nt][1] * rdlo};
        float2 ohi = {acc[nt][2] * rdhi, acc[nt][3] * rdhi};
        *reinterpret_cast<float2*>(&g_agg[rlo * DDIM + 8 * nt + coff]) = olo;
        *reinterpret_cast<float2*>(&g_agg[rhi * DDIM + 8 * nt + coff]) = ohi;
    }
}

// ==================== Kernel 3: update MLP ====================
__global__ __launch_bounds__(128) void upd_kernel(
    const float* __restrict__ states, const float* __restrict__ W1,
    const float* __restrict__ b1,     const float* __restrict__ W2,
    const float* __restrict__ b2,     float* __restrict__ out)
{
    __shared__ float sW1[2 * DDIM * HDIM];
    __shared__ float sW2[HDIM * DDIM];
    const int tid = threadIdx.x;
    for (int i = tid; i < 2 * DDIM * HDIM; i += 128) sW1[i] = W1[i];
    for (int i = tid; i < HDIM * DDIM; i += 128)     sW2[i] = W2[i];
    __syncthreads();

    const int row = blockIdx.x * 128 + tid;
    float x[2 * DDIM];
    const float4* sp = reinterpret_cast<const float4*>(states + (size_t)row * DDIM);
    const float4* gp = reinterpret_cast<const float4*>(g_agg  + (size_t)row * DDIM);
    #pragma unroll
    for (int j4 = 0; j4 < DDIM / 4; j4++) {
        float4 v = sp[j4];
        x[4*j4+0] = v.x; x[4*j4+1] = v.y; x[4*j4+2] = v.z; x[4*j4+3] = v.w;
        float4 g = gp[j4];
        x[DDIM+4*j4+0] = g.x; x[DDIM+4*j4+1] = g.y;
        x[DDIM+4*j4+2] = g.z; x[DDIM+4*j4+3] = g.w;
    }
    float m[DDIM];
    #pragma unroll
    for (int d = 0; d < DDIM; d++) m[d] = __ldg(&b2[d]);

    #pragma unroll 2
    for (int hg = 0; hg < HDIM / 4; hg++) {
        float4 hid = __ldg(reinterpret_cast<const float4*>(b1) + hg);
        #pragma unroll
        for (int j = 0; j < 2 * DDIM; j++) {
            float4 w = *reinterpret_cast<const float4*>(&sW1[j * HDIM + 4 * hg]);
            hid.x += x[j] * w.x; hid.y += x[j] * w.y;
            hid.z += x[j] * w.z; hid.w += x[j] * w.w;
        }
        float rr[4] = {fmaxf(hid.x, 0.f), fmaxf(hid.y, 0.f),
                       fmaxf(hid.z, 0.f), fmaxf(hid.w, 0.f)};
        #pragma unroll
        for (int e = 0; e < 4; e++) {
            float r = rr[e];
            #pragma unroll
            for (int d4 = 0; d4 < DDIM / 4; d4++) {
                float4 w = *reinterpret_cast<const float4*>(&sW2[(4*hg+e) * DDIM + 4*d4]);
                m[4*d4+0] += r * w.x; m[4*d4+1] += r * w.y;
                m[4*d4+2] += r * w.z; m[4*d4+3] += r * w.w;
            }
        }
    }
    float4* op = reinterpret_cast<float4*>(out + (size_t)row * DDIM);
    #pragma unroll
    for (int d4 = 0; d4 < DDIM / 4; d4++) {
        float4 o;
        o.x = m[4*d4+0]; o.y = m[4*d4+1]; o.z = m[4*d4+2]; o.w = m[4*d4+3];
        op[d4] = o;
    }
}

// ==================== launch ====================
extern "C" void kernel_launch(void* const* d_in, const int* in_sizes, int n_in,
                              void* d_out, int out_size)
{
    const float* states = (const float*)d_in[0];
    const float* adj    = (const float*)d_in[1];
    const float* mW1    = (const float*)d_in[2];
    const float* mb1    = (const float*)d_in[3];
    const float* mW2    = (const float*)d_in[4];
    const float* mb2    = (const float*)d_in[5];
    const float* uW1    = (const float*)d_in[6];
    const float* ub1    = (const float*)d_in[7];
    const float* uW2    = (const float*)d_in[8];
    const float* ub2    = (const float*)d_in[9];
    float* out = (float*)d_out;

    cudaFuncSetAttribute(agg_kernel, cudaFuncAttributeMaxDynamicSharedMemorySize, SMEM_TOTAL);

    msg_kernel<<<NROWS / 128, 128>>>(states, mW1, mb1, mW2, mb2);
    agg_kernel<<<NROWS / 128, 256, SMEM_TOTAL>>>(adj);
    upd_kernel<<<NROWS / 128, 128>>>(states, uW1, ub1, uW2, ub2, out);
}